// round 2
// baseline (speedup 1.0000x reference)
#include <cuda_runtime.h>

// VQ-VAE bottleneck — reference-rounding-faithful emulation.
//   x: [32, 64, 64, 64] f32 (B, C=64, H, W), codebook: [512, 64] f32
//   out: quantized [32,64,64,64] f32 (8388608 elts) + loss scalar (1 elt)
//
// Reference computes (fp32 throughout):
//   d_k = RN( RN(||z||^2 + ||e_k||^2) - 2*(z.e_k) ),  argmin_k (first min)
// with ||z||^2 ~ 64 => distances quantized at ulp(64)=2^-17. A single argmin
// flip exceeds the 1e-3 threshold, so we emulate:
//   ||z||^2 : sequential fp32, separate mul+add (XLA CPU reduce of x*x)
//   ||e||^2 : same
//   z.e_k   : sequential fp32 FMA over c ascending (Eigen gebp depth loop)
// Output is the straight-through value RN(x + RN(q - x)), not q itself.

#define NPOS   131072
#define CDIM   64
#define KCODES 512
#define HW     4096
#define NELEM  8388608

// Z summation-order hypothesis selector (probe knob for future rounds):
// 0 = sequential mul+add (this round)
// 1 = NEON 4-lane vertical + pairwise tree
#define Z_MODE 0

__device__ float g_loss_sum;

__global__ void vq_reset_kernel() { g_loss_sum = 0.0f; }

__global__ void vq_finalize_kernel(float* out, int loss_idx) {
    // loss = q_latent + 0.25*e_latent, both equal to L = mean((q-x)^2):
    // ref computes RN(L + RN(0.25*L)); 0.25*L is exact.
    float L = g_loss_sum * (1.0f / (float)NELEM);
    out[loss_idx] = __fadd_rn(L, 0.25f * L);
}

// dynamic smem: [KCODES*CDIM] codebook + [KCODES] ||e_k||^2 (ref rounding)
extern __shared__ float sm[];

__global__ __launch_bounds__(256, 1)
void vq_main_kernel(const float* __restrict__ x,
                    const float* __restrict__ cb,
                    float* __restrict__ out) {
    float* cb_s = sm;                      // 512*64 floats = 128 KB
    float* e2_s = sm + KCODES * CDIM;      // 512 floats

    // load codebook into smem (bit-exact copy)
    {
        float4*       dst = (float4*)cb_s;
        const float4* src = (const float4*)cb;
        for (int i = threadIdx.x; i < KCODES * CDIM / 4; i += blockDim.x)
            dst[i] = src[i];
    }
    __syncthreads();

    // ||e_k||^2: sequential fp32, separate mul then add (matches XLA reduce)
    for (int k = threadIdx.x; k < KCODES; k += blockDim.x) {
        float s = 0.0f;
        #pragma unroll
        for (int c = 0; c < CDIM; c++) {
            float e = cb_s[k * CDIM + c];
            s = __fadd_rn(s, __fmul_rn(e, e));
        }
        e2_s[k] = s;
    }
    __syncthreads();

    int p  = blockIdx.x * blockDim.x + threadIdx.x;   // 0..131071
    int b  = p >> 12;
    int hw = p & (HW - 1);

    const float* xp = x + (size_t)b * CDIM * HW + hw;
    float z[CDIM];
    #pragma unroll
    for (int c = 0; c < CDIM; c++) z[c] = xp[(size_t)c * HW];   // coalesced per c

    // ||z||^2 with reference summation order
    float Z = 0.0f;
#if Z_MODE == 0
    #pragma unroll
    for (int c = 0; c < CDIM; c++)
        Z = __fadd_rn(Z, __fmul_rn(z[c], z[c]));
#else
    {
        float l0 = 0.f, l1 = 0.f, l2 = 0.f, l3 = 0.f;
        #pragma unroll
        for (int i = 0; i < CDIM / 4; i++) {
            l0 = __fadd_rn(l0, __fmul_rn(z[4*i+0], z[4*i+0]));
            l1 = __fadd_rn(l1, __fmul_rn(z[4*i+1], z[4*i+1]));
            l2 = __fadd_rn(l2, __fmul_rn(z[4*i+2], z[4*i+2]));
            l3 = __fadd_rn(l3, __fmul_rn(z[4*i+3], z[4*i+3]));
        }
        Z = __fadd_rn(__fadd_rn(l0, l1), __fadd_rn(l2, l3));
    }
#endif

    // argmin over 512 codewords; 8 codewords in flight for ILP, each dot
    // strictly sequential FMA over c ascending (Eigen depth-loop order).
    float bestd = 3.402823466e38f;
    int   best  = 0;
    const float4* cbs4 = (const float4*)cb_s;

    for (int k0 = 0; k0 < KCODES; k0 += 8) {
        float m[8];
        #pragma unroll
        for (int g = 0; g < 8; g++) m[g] = 0.0f;

        #pragma unroll
        for (int j = 0; j < CDIM / 4; j++) {
            #pragma unroll
            for (int g = 0; g < 8; g++) {
                float4 e = cbs4[(k0 + g) * (CDIM / 4) + j];   // LDS.128 broadcast
                m[g] = __fmaf_rn(z[4*j+0], e.x, m[g]);
                m[g] = __fmaf_rn(z[4*j+1], e.y, m[g]);
                m[g] = __fmaf_rn(z[4*j+2], e.z, m[g]);
                m[g] = __fmaf_rn(z[4*j+3], e.w, m[g]);
            }
        }

        #pragma unroll
        for (int g = 0; g < 8; g++) {
            float t = __fadd_rn(Z, e2_s[k0 + g]);       // RN(Z + B_k)
            float d = __fadd_rn(t, -2.0f * m[g]);       // RN(t - 2M), 2M exact
            if (d < bestd) { bestd = d; best = k0 + g; }  // first-min wins
        }
    }

    // write straight-through output RN(x + RN(q - x)); accumulate ref SSE
    float* op  = out + (size_t)b * CDIM * HW + hw;
    float  sse = 0.0f;
    #pragma unroll
    for (int c = 0; c < CDIM; c++) {
        float q    = cb_s[best * CDIM + c];
        float diff = __fadd_rn(q, -z[c]);               // RN(q - x)
        op[(size_t)c * HW] = __fadd_rn(z[c], diff);     // RN(x + RN(q - x))
        sse = __fadd_rn(sse, __fmul_rn(diff, diff));
    }

    #pragma unroll
    for (int o = 16; o; o >>= 1) sse += __shfl_xor_sync(0xffffffffu, sse, o);
    if ((threadIdx.x & 31) == 0) atomicAdd(&g_loss_sum, sse);
}

extern "C" void kernel_launch(void* const* d_in, const int* in_sizes, int n_in,
                              void* d_out, int out_size) {
    const float* x   = (const float*)d_in[0];
    const float* cb  = (const float*)d_in[1];
    float*       out = (float*)d_out;

    const int smem_bytes = (KCODES * CDIM + KCODES) * (int)sizeof(float);  // 133120
    cudaFuncSetAttribute(vq_main_kernel,
                         cudaFuncAttributeMaxDynamicSharedMemorySize, smem_bytes);

    vq_reset_kernel<<<1, 1>>>();
    vq_main_kernel<<<NPOS / 256, 256, smem_bytes>>>(x, cb, out);
    if (out_size > NELEM)
        vq_finalize_kernel<<<1, 1>>>(out, out_size - 1);
}